// round 15
// baseline (speedup 1.0000x reference)
#include <cuda_runtime.h>
#include <cuda_bf16.h>
#include <cstdint>

#define B_  8
#define T_  2048
#define D_  544
#define H_  8
#define DK_ 64
#define DV_ 128
#define KDIM_ 512
#define VDIM_ 1024
#define HID_ 1632
#define NTOK (B_*T_)          // 16384
#define M1   3088             // 512+512+1024+8+8+1024 fused out dims

// ---------------- scratch (device globals; no runtime alloc allowed) --------
static __device__ __nv_bfloat16 g_hb   [NTOK * D_];
static __device__ __nv_bfloat16 g_wcatb[M1 * D_];
static __device__ float         g_c1   [(size_t)NTOK * M1];
static __device__ float         g_q    [(size_t)NTOK * KDIM_];
static __device__ float         g_k    [(size_t)NTOK * KDIM_];
static __device__ float         g_v    [(size_t)NTOK * VDIM_];
static __device__ float         g_beta [NTOK * H_];
static __device__ float         g_g    [NTOK * H_];
static __device__ float         g_o    [(size_t)NTOK * VDIM_];
static __device__ __nv_bfloat16 g_ogb  [(size_t)NTOK * VDIM_];
static __device__ __nv_bfloat16 g_wob  [D_ * VDIM_];
static __device__ float         g_xmid [NTOK * D_];
static __device__ __nv_bfloat16 g_h2b  [NTOK * D_];
static __device__ __nv_bfloat16 g_wfcb [HID_ * D_];
static __device__ __nv_bfloat16 g_m2b  [(size_t)NTOK * HID_];
static __device__ __nv_bfloat16 g_wprojb[D_ * HID_];

// ============================ helpers ========================================
__device__ __forceinline__ uint32_t smem_u32(const void* p) {
    uint32_t a;
    asm("{ .reg .u64 t; cvta.to.shared.u64 t, %1; cvt.u32.u64 %0, t; }" : "=r"(a) : "l"(p));
    return a;
}
__device__ __forceinline__ uint32_t f2bf2(float lo, float hi) {
    uint32_t r;
    asm("cvt.rn.bf16x2.f32 %0, %1, %2;" : "=r"(r) : "f"(hi), "f"(lo));
    return r;
}
__device__ __forceinline__ void ldsm_x4(uint32_t* r, uint32_t addr) {
    asm volatile("ldmatrix.sync.aligned.m8n8.x4.shared.b16 {%0,%1,%2,%3}, [%4];"
        : "=r"(r[0]), "=r"(r[1]), "=r"(r[2]), "=r"(r[3]) : "r"(addr));
}
__device__ __forceinline__ void ldsm_x2(uint32_t* r, uint32_t addr) {
    asm volatile("ldmatrix.sync.aligned.m8n8.x2.shared.b16 {%0,%1}, [%2];"
        : "=r"(r[0]), "=r"(r[1]) : "r"(addr));
}
__device__ __forceinline__ void mma_bf16(float* c, const uint32_t* a, const uint32_t* b) {
    asm volatile(
        "mma.sync.aligned.m16n8k16.row.col.f32.bf16.bf16.f32 "
        "{%0,%1,%2,%3}, {%4,%5,%6,%7}, {%8,%9}, {%0,%1,%2,%3};"
        : "+f"(c[0]), "+f"(c[1]), "+f"(c[2]), "+f"(c[3])
        : "r"(a[0]), "r"(a[1]), "r"(a[2]), "r"(a[3]), "r"(b[0]), "r"(b[1]));
}

// ============== bf16 mma.sync GEMM: C[M,N] = A[M,K] @ B[N,K]^T ===============
// ROUND-6 VERBATIM (verified best): 128x128 block tile, BK=32, 256 threads =
// 8 warps (2 warpM x 4 warpN), warp tile 64x32 = 4x4 m16n8k16 fragments.
// LDG->register prefetch->STS, double-buffered static SMEM, 80B row stride.
// modes: 0: fp32 C=acc; 1: fp32 C=res+scale[col]*acc; 2: bf16 C=relu(acc)^2
#define SST 40
__global__ void __launch_bounds__(256)
tmma_gemm(const __nv_bfloat16* __restrict__ A, const __nv_bfloat16* __restrict__ B,
          void* __restrict__ Cv, int N, int K, int mode,
          const float* __restrict__ res, const float* __restrict__ scale) {
    __shared__ __align__(16) uint16_t sA[2][128 * SST];
    __shared__ __align__(16) uint16_t sB[2][128 * SST];

    const int tid  = threadIdx.x;
    const int wid  = tid >> 5, lane = tid & 31;
    const int warpM = wid & 1;
    const int warpN = wid >> 1;
    const int rowBase = blockIdx.y * 128;
    const int colBase = blockIdx.x * 128;

    const int r0 = lane >> 2;
    const int c0 = lane & 3;

    float acc[4][4][4];
    #pragma unroll
    for (int mt = 0; mt < 4; mt++)
        #pragma unroll
        for (int nt = 0; nt < 4; nt++)
            #pragma unroll
            for (int i = 0; i < 4; i++) acc[mt][nt][i] = 0.f;

    const int NK = K >> 5;

    const int lr = tid >> 2;
    const int lch = (tid & 3) * 8;

    const uint32_t aBase = smem_u32(&sA[0][0]);
    const uint32_t bBase = smem_u32(&sB[0][0]);
    const uint32_t stageBytes = 128 * SST * 2;
    const uint32_t aRowOff = (uint32_t)((warpM * 64 + (lane & 15)) * SST * 2 + (lane >> 4) * 16);
    const uint32_t bRowOff = (uint32_t)((warpN * 32 + (lane & 7)) * SST * 2 + ((lane >> 3) & 1) * 16);

    #pragma unroll
    for (int it = 0; it < 2; it++) {
        int r = lr + it * 64;
        uint4 a4 = *(const uint4*)(A + (size_t)(rowBase + r) * K + lch);
        int bn = colBase + r;
        uint4 b4 = (bn < N) ? *(const uint4*)(B + (size_t)bn * K + lch)
                            : make_uint4(0u, 0u, 0u, 0u);
        *(uint4*)&sA[0][r * SST + lch] = a4;
        *(uint4*)&sB[0][r * SST + lch] = b4;
    }
    __syncthreads();

    for (int kt = 0; kt < NK; kt++) {
        const int cur = kt & 1, nxt = cur ^ 1;
        const bool have_next = (kt + 1 < NK);
        uint4 ra[2], rb[2];
        if (have_next) {
            int kb = (kt + 1) * 32;
            #pragma unroll
            for (int it = 0; it < 2; it++) {
                int r = lr + it * 64;
                ra[it] = *(const uint4*)(A + (size_t)(rowBase + r) * K + kb + lch);
                int bn = colBase + r;
                rb[it] = (bn < N) ? *(const uint4*)(B + (size_t)bn * K + kb + lch)
                                  : make_uint4(0u, 0u, 0u, 0u);
            }
        }

        const uint32_t aS = aBase + cur * stageBytes + aRowOff;
        const uint32_t bS = bBase + cur * stageBytes + bRowOff;
        #pragma unroll
        for (int ks = 0; ks < 2; ks++) {
            uint32_t af[4][4], bf[4][2];
            #pragma unroll
            for (int mt = 0; mt < 4; mt++)
                ldsm_x4(af[mt], aS + (uint32_t)(mt * 16 * SST) * 2 + ks * 32);
            #pragma unroll
            for (int nt = 0; nt < 4; nt++)
                ldsm_x2(bf[nt], bS + (uint32_t)(nt * 8 * SST) * 2 + ks * 32);
            #pragma unroll
            for (int mt = 0; mt < 4; mt++)
                #pragma unroll
                for (int nt = 0; nt < 4; nt++)
                    mma_bf16(acc[mt][nt], af[mt], bf[nt]);
        }

        if (have_next) {
            #pragma unroll
            for (int it = 0; it < 2; it++) {
                int r = lr + it * 64;
                *(uint4*)&sA[nxt][r * SST + lch] = ra[it];
                *(uint4*)&sB[nxt][r * SST + lch] = rb[it];
            }
        }
        __syncthreads();
    }

    #pragma unroll
    for (int mt = 0; mt < 4; mt++) {
        #pragma unroll
        for (int half = 0; half < 2; half++) {
            int row = rowBase + warpM * 64 + mt * 16 + r0 + half * 8;
            #pragma unroll
            for (int nt = 0; nt < 4; nt++) {
                int col = colBase + warpN * 32 + nt * 8 + 2 * c0;
                if (col < N) {
                    float v0 = acc[mt][nt][half * 2 + 0];
                    float v1 = acc[mt][nt][half * 2 + 1];
                    if (mode == 1) {
                        const float* rp = res + (size_t)row * N + col;
                        v0 = rp[0] + scale[col] * v0;
                        v1 = rp[1] + scale[col + 1] * v1;
                        *(float2*)((float*)Cv + (size_t)row * N + col) = make_float2(v0, v1);
                    } else if (mode == 2) {
                        v0 = fmaxf(v0, 0.f); v0 = v0 * v0;
                        v1 = fmaxf(v1, 0.f); v1 = v1 * v1;
                        ((uint32_t*)Cv)[((size_t)row * N + col) >> 1] = f2bf2(v0, v1);
                    } else {
                        *(float2*)((float*)Cv + (size_t)row * N + col) = make_float2(v0, v1);
                    }
                }
            }
        }
    }
}

// ---------------- fp32 -> bf16 copy ------------------------------------------
__global__ void cvt_bf16(const float* __restrict__ src, __nv_bfloat16* __restrict__ dst, int n) {
    int i = (blockIdx.x * blockDim.x + threadIdx.x) * 2;
    if (i < n) {
        float2 v = *(const float2*)(src + i);
        *(uint32_t*)(dst + i) = f2bf2(v.x, v.y);
    }
}

// ---------------- pack fused weight matrix [3088 x 544] -> bf16 --------------
__global__ void pack_wcat(const float* __restrict__ Wq, const float* __restrict__ Wk,
                          const float* __restrict__ Wv, const float* __restrict__ Wb,
                          const float* __restrict__ Wa, const float* __restrict__ Wg) {
    int idx = blockIdx.x * blockDim.x + threadIdx.x;
    if (idx >= M1 * D_) return;
    int row = idx / D_, col = idx % D_;
    float v;
    if      (row < 512)  v = Wq[row * D_ + col];
    else if (row < 1024) v = Wk[(row - 512) * D_ + col];
    else if (row < 2048) v = Wv[(row - 1024) * D_ + col];
    else if (row < 2056) v = Wb[(row - 2048) * D_ + col];
    else if (row < 2064) v = Wa[(row - 2056) * D_ + col];
    else                 v = Wg[(row - 2064) * D_ + col];
    g_wcatb[idx] = __float2bfloat16(v);
}

// ---------------- parameter-free RMSNorm over D=544 -> bf16 ------------------
__global__ void rms_kernel(const float* __restrict__ x, __nv_bfloat16* __restrict__ y) {
    int row = blockIdx.x;
    int tid = threadIdx.x;          // blockDim = 544 (17 warps)
    float v = x[(size_t)row * D_ + tid];
    float s = v * v;
    #pragma unroll
    for (int o = 16; o; o >>= 1) s += __shfl_xor_sync(0xffffffffu, s, o);
    __shared__ float ws[17];
    if ((tid & 31) == 0) ws[tid >> 5] = s;
    __syncthreads();
    if (tid < 32) {
        float t = (tid < 17) ? ws[tid] : 0.f;
        #pragma unroll
        for (int o = 16; o; o >>= 1) t += __shfl_xor_sync(0xffffffffu, t, o);
        if (tid == 0) ws[0] = t;
    }
    __syncthreads();
    float scale = rsqrtf(ws[0] * (1.0f / (float)D_) + 1e-6f);
    y[(size_t)row * D_ + tid] = __float2bfloat16(v * scale);
}

// ------- causal depthwise conv (K=4) + silu, 4 tokens per thread -------------
__global__ void conv_silu_kernel(const float* __restrict__ wq, const float* __restrict__ wk,
                                 const float* __restrict__ wv) {
    int idx = blockIdx.x * blockDim.x + threadIdx.x;   // (NTOK/4) * 2048
    if (idx >= (NTOK / 4) * 2048) return;
    int c   = idx & 2047;
    int grp = idx >> 11;
    int b   = grp >> 9;
    int t0  = (grp & 511) * 4;

    const float* w; float* outp; int ostride;
    if (c < 512)        { w = wq + c * 4;          outp = g_q + ((size_t)b * T_ + t0) * KDIM_ + c;          ostride = KDIM_; }
    else if (c < 1024)  { w = wk + (c - 512) * 4;  outp = g_k + ((size_t)b * T_ + t0) * KDIM_ + (c - 512);  ostride = KDIM_; }
    else                { w = wv + (c - 1024) * 4; outp = g_v + ((size_t)b * T_ + t0) * VDIM_ + (c - 1024); ostride = VDIM_; }

    float w0 = w[0], w1 = w[1], w2 = w[2], w3 = w[3];
    float xs[7];
    #pragma unroll
    for (int i = 0; i < 7; i++) {
        int tt = t0 - 3 + i;
        xs[i] = (tt >= 0) ? g_c1[((size_t)b * T_ + tt) * M1 + c] : 0.f;
    }
    #pragma unroll
    for (int r = 0; r < 4; r++) {
        float a = xs[r] * w0 + xs[r + 1] * w1 + xs[r + 2] * w2 + xs[r + 3] * w3;
        outp[(size_t)r * ostride] = a / (1.f + expf(-a));
    }
}

// ---------------- beta / log-decay g ----------------------------------------
__global__ void betag_kernel(const float* __restrict__ A_log, const float* __restrict__ dt_bias) {
    int idx = blockIdx.x * blockDim.x + threadIdx.x;   // NTOK * H
    if (idx >= NTOK * H_) return;
    int row = idx >> 3, h = idx & 7;
    float zb = g_c1[(size_t)row * M1 + 2048 + h];
    float za = g_c1[(size_t)row * M1 + 2056 + h];
    g_beta[idx] = 2.f / (1.f + expf(-zb));
    float z = za + dt_bias[h];
    float sp = (z > 20.f) ? z : log1pf(expf(z));
    g_g[idx] = -expf(A_log[h]) * sp;
}

// ---------------- l2-normalize q (with DK^-0.5) and k ------------------------
__global__ void l2_kernel() {
    int gwarp = (blockIdx.x * blockDim.x + threadIdx.x) >> 5;
    int lane  = threadIdx.x & 31;
    const int nvec = NTOK * H_;
    float* base; float extra;
    if (gwarp < nvec) { base = g_q + (size_t)gwarp * DK_;          extra = 0.125f; }
    else              { base = g_k + (size_t)(gwarp - nvec) * DK_; extra = 1.0f;   }
    float a = base[lane], b = base[lane + 32];
    float s = a * a + b * b;
    #pragma unroll
    for (int o = 16; o; o >>= 1) s += __shfl_xor_sync(0xffffffffu, s, o);
    float r = rsqrtf(s + 1e-6f) * extra;
    base[lane] = a * r;
    base[lane + 32] = b * r;
}

// ---------------- gated delta rule scan --------------------------------------
// ROUND-6 partition and per-step math (identical numerics); 32-deep q/k smem
// ring, ONE __syncthreads per SIXTEEN timesteps (extends rounds 12-14's win).
// block = (b,h,vhalf): 128 CTAs. 128 threads: thread = jloc*2 + kh.
// Thread owns S[kh*32 : kh*32+32][vhalf*64 + jloc]; pairs combine via shfl.
__global__ void __launch_bounds__(128)
delta_kernel() {
    int bh = blockIdx.x >> 1;
    int vh = blockIdx.x & 1;
    int b = bh >> 3, h = bh & 7;
    int tid = threadIdx.x;
    int jloc = tid >> 1;
    int kh   = tid & 1;
    int j = vh * 64 + jloc;
    const int kofs = kh * 32;

    __shared__ float sq[32][64], sk[32][64];
    float S[32];
    #pragma unroll
    for (int i = 0; i < 32; i++) S[i] = 0.f;

    const size_t tok0 = (size_t)b * T_ * H_ + h;
    const float* qb = g_q + tok0 * DK_;
    const float* kb = g_k + tok0 * DK_;
    const float* vb = g_v + tok0 * DV_;
    float*       ob = g_o + tok0 * DV_;
    const float* gb = g_g + tok0;
    const float* bbp = g_beta + tok0;

    // prologue: steps 0..15 into ring slots 0..15
    float vv[32], gg[32], bbv[32];
    #pragma unroll
    for (int s = 0; s < 16; s++) {
        size_t off = (size_t)s * H_;
        if (tid < 64) sq[s][tid] = qb[off * DK_ + tid];
        else          sk[s][tid - 64] = kb[off * DK_ + (tid - 64)];
        vv[s] = vb[off * DV_ + j];
        gg[s] = gb[off];
        bbv[s] = bbp[off];
    }
    __syncthreads();

    for (int t = 0; t < T_; t += 16) {
        // prefetch steps t+16..t+31 into ring slots (t+16)&31..(t+31)&31
        // (consumed in the previous iteration, before the last barrier)
        if (t + 16 < T_) {
            #pragma unroll
            for (int s = 0; s < 16; s++) {
                size_t off = (size_t)(t + 16 + s) * H_;
                int slot = (t + 16 + s) & 31;
                if (tid < 64) sq[slot][tid] = qb[off * DK_ + tid];
                else          sk[slot][tid - 64] = kb[off * DK_ + (tid - 64)];
                vv[16 + s] = vb[off * DV_ + j];
                gg[16 + s] = gb[off];
                bbv[16 + s] = bbp[off];
            }
        }

        #pragma unroll
        for (int s = 0; s < 16; s++) {
            const int buf = (t + s) & 31;
            float eg = expf(gg[s]);

            float kk[32];
            #pragma unroll
            for (int i = 0; i < 32; i += 4) {
                float4 t4 = *(const float4*)&sk[buf][kofs + i];
                kk[i] = t4.x; kk[i+1] = t4.y; kk[i+2] = t4.z; kk[i+3] = t4.w;
            }
            float kv0 = 0.f, kv1 = 0.f, kv2 = 0.f, kv3 = 0.f;
            #pragma unroll
            for (int i = 0; i < 32; i += 4) {
                kv0 += S[i + 0] * kk[i + 0];
                kv1 += S[i + 1] * kk[i + 1];
                kv2 += S[i + 2] * kk[i + 2];
                kv3 += S[i + 3] * kk[i + 3];
            }
            float kv = (kv0 + kv1) + (kv2 + kv3);
            kv += __shfl_xor_sync(0xffffffffu, kv, 1);
            float vres = (vv[s] - eg * kv) * bbv[s];

            float o0 = 0.f, o1 = 0.f, o2 = 0.f, o3 = 0.f;
            #pragma unroll
            for (int i = 0; i < 32; i += 4) {
                float4 q4 = *(const float4*)&sq[buf][kofs + i];
                S[i + 0] = eg * S[i + 0] + kk[i + 0] * vres; o0 += S[i + 0] * q4.x;
                S[i + 1] = eg * S[i + 1] + kk[i + 1] * vres; o1 += S[i + 1] * q4.y;
                S[i + 2] = eg * S[i + 2] + kk[i + 2] * vres; o2 += S[i + 2] * q4.z;
                S[i + 3] = eg * S[i + 3] + kk[i + 3] * vres; o3 += S[i + 3] * q4.w;
            }
            float o = (o0 + o1) + (o2 + o3);
            o += __shfl_xor_sync(0xffffffffu, o, 1);
            if (kh == 0) ob[(size_t)(t + s) * H_ * DV_ + j] = o;
        }

        #pragma unroll
        for (int s = 0; s < 16; s++) {
            vv[s] = vv[16 + s]; gg[s] = gg[16 + s]; bbv[s] = bbv[16 + s];
        }
        __syncthreads();
    }
}

// -------- gated RMSNorm on o: rms(o)*w*silu(gate) -> bf16 --------------------
__global__ void gatednorm_kernel(const float* __restrict__ o_norm_w) {
    int gvec = blockIdx.x * 8 + (threadIdx.x >> 5);   // (row, h)
    int lane = threadIdx.x & 31;
    int row = gvec >> 3, h = gvec & 7;

    const float* obase = g_o + (size_t)row * VDIM_ + h * DV_;
    float4 ov = *(const float4*)(obase + lane * 4);
    float s = ov.x * ov.x + ov.y * ov.y + ov.z * ov.z + ov.w * ov.w;
    #pragma unroll
    for (int off = 16; off; off >>= 1) s += __shfl_xor_sync(0xffffffffu, s, off);
    float scale = rsqrtf(s * (1.0f / (float)DV_) + 1e-5f);

    const float* gptr = g_c1 + (size_t)row * M1 + 2064 + h * DV_ + lane * 4;
    float4 gv = *(const float4*)gptr;
    float4 wv = *(const float4*)(o_norm_w + lane * 4);
    float r0 = ov.x * scale * wv.x * (gv.x / (1.f + expf(-gv.x)));
    float r1 = ov.y * scale * wv.y * (gv.y / (1.f + expf(-gv.y)));
    float r2 = ov.z * scale * wv.z * (gv.z / (1.f + expf(-gv.z)));
    float r3 = ov.w * scale * wv.w * (gv.w / (1.f + expf(-gv.w)));
    *(uint2*)(g_ogb + (size_t)row * VDIM_ + h * DV_ + lane * 4) =
        make_uint2(f2bf2(r0, r1), f2bf2(r2, r3));
}

// ---------------- launch ------------------------------------------------------
static inline int cdiv(int a, int b) { return (a + b - 1) / b; }

extern "C" void kernel_launch(void* const* d_in, const int* in_sizes, int n_in,
                              void* d_out, int out_size) {
    const float* x       = (const float*)d_in[0];
    const float* Wq      = (const float*)d_in[1];
    const float* Wk      = (const float*)d_in[2];
    const float* Wv      = (const float*)d_in[3];
    const float* Wb      = (const float*)d_in[4];
    const float* Wa      = (const float*)d_in[5];
    const float* Wg      = (const float*)d_in[6];
    const float* Wo      = (const float*)d_in[7];
    const float* conv_q  = (const float*)d_in[8];
    const float* conv_k  = (const float*)d_in[9];
    const float* conv_v  = (const float*)d_in[10];
    const float* A_log   = (const float*)d_in[11];
    const float* dt_bias = (const float*)d_in[12];
    const float* o_norm_w= (const float*)d_in[13];
    const float* W_fc    = (const float*)d_in[14];
    const float* W_proj  = (const float*)d_in[15];
    const float* gdn_scale = (const float*)d_in[16];
    const float* mlp_scale = (const float*)d_in[17];
    float* out = (float*)d_out;

    __nv_bfloat16 *p_hb, *p_wcatb, *p_ogb, *p_wob, *p_h2b, *p_wfcb, *p_m2b, *p_wprojb;
    float *p_c1, *p_xmid;
    cudaGetSymbolAddress((void**)&p_hb,     g_hb);
    cudaGetSymbolAddress((void**)&p_wcatb,  g_wcatb);
    cudaGetSymbolAddress((void**)&p_c1,     g_c1);
    cudaGetSymbolAddress((void**)&p_ogb,    g_ogb);
    cudaGetSymbolAddress((void**)&p_wob,    g_wob);
    cudaGetSymbolAddress((void**)&p_xmid,   g_xmid);
    cudaGetSymbolAddress((void**)&p_h2b,    g_h2b);
    cudaGetSymbolAddress((void**)&p_wfcb,   g_wfcb);
    cudaGetSymbolAddress((void**)&p_m2b,    g_m2b);
    cudaGetSymbolAddress((void**)&p_wprojb, g_wprojb);

    // 0) weight conversions (bf16-resident operands)
    pack_wcat<<<cdiv(M1 * D_, 256), 256>>>(Wq, Wk, Wv, Wb, Wa, Wg);
    cvt_bf16<<<cdiv(D_ * VDIM_ / 2, 256), 256>>>(Wo, p_wob, D_ * VDIM_);
    cvt_bf16<<<cdiv(HID_ * D_ / 2, 256), 256>>>(W_fc, p_wfcb, HID_ * D_);
    cvt_bf16<<<cdiv(D_ * HID_ / 2, 256), 256>>>(W_proj, p_wprojb, D_ * HID_);

    // 1) h = rmsnorm(x) -> bf16
    rms_kernel<<<NTOK, D_>>>(x, p_hb);

    // 2) C1 = h @ Wcat^T   (16384 x 3088), K=544
    tmma_gemm<<<dim3(cdiv(M1, 128), NTOK / 128), 256>>>(
        p_hb, p_wcatb, p_c1, M1, D_, 0, nullptr, nullptr);

    // 3) conv + silu  -> q,k,v
    conv_silu_kernel<<<cdiv((NTOK / 4) * 2048, 256), 256>>>(conv_q, conv_k, conv_v);

    // 4) beta, g
    betag_kernel<<<cdiv(NTOK * H_, 256), 256>>>(A_log, dt_bias);

    // 5) l2 norm q (with DK^-0.5), k
    l2_kernel<<<cdiv(NTOK * H_ * 2 * 32, 256), 256>>>();

    // 6) gated delta rule scan (round-6 shape, 1 barrier per 16 steps)
    delta_kernel<<<B_ * H_ * 2, 128>>>();

    // 7) gated RMSNorm(o) * silu(gate) -> bf16
    gatednorm_kernel<<<NTOK * H_ / 8, 256>>>(o_norm_w);

    // 8) x_mid = x + gdn_scale * (og @ Wo^T), K=1024
    tmma_gemm<<<dim3(cdiv(D_, 128), NTOK / 128), 256>>>(
        p_ogb, p_wob, p_xmid, D_, VDIM_, 1, x, gdn_scale);

    // 9) h2 = rmsnorm(x_mid) -> bf16
    rms_kernel<<<NTOK, D_>>>(p_xmid, p_h2b);

    // 10) m2 = relu(h2 @ W_fc^T)^2 -> bf16, K=544
    tmma_gemm<<<dim3(cdiv(HID_, 128), NTOK / 128), 256>>>(
        p_h2b, p_wfcb, p_m2b, HID_, D_, 2, nullptr, nullptr);

    // 11) out = x_mid + mlp_scale * (m2 @ W_proj^T), K=1632
    tmma_gemm<<<dim3(cdiv(D_, 128), NTOK / 128), 256>>>(
        p_m2b, p_wprojb, out, D_, HID_, 1, p_xmid, mlp_scale);
}

// round 16
// speedup vs baseline: 1.0315x; 1.0315x over previous
#include <cuda_runtime.h>
#include <cuda_bf16.h>
#include <cstdint>

#define B_  8
#define T_  2048
#define D_  544
#define H_  8
#define DK_ 64
#define DV_ 128
#define KDIM_ 512
#define VDIM_ 1024
#define HID_ 1632
#define NTOK (B_*T_)          // 16384
#define M1   3088             // 512+512+1024+8+8+1024 fused out dims

// ---------------- scratch (device globals; no runtime alloc allowed) --------
static __device__ __nv_bfloat16 g_hb   [NTOK * D_];
static __device__ __nv_bfloat16 g_wcatb[M1 * D_];
static __device__ float         g_c1   [(size_t)NTOK * M1];
static __device__ float         g_q    [(size_t)NTOK * KDIM_];
static __device__ float         g_k    [(size_t)NTOK * KDIM_];
static __device__ float         g_v    [(size_t)NTOK * VDIM_];
static __device__ float         g_beta [NTOK * H_];
static __device__ float         g_g    [NTOK * H_];
static __device__ float         g_o    [(size_t)NTOK * VDIM_];
static __device__ __nv_bfloat16 g_ogb  [(size_t)NTOK * VDIM_];
static __device__ __nv_bfloat16 g_wob  [D_ * VDIM_];
static __device__ float         g_xmid [NTOK * D_];
static __device__ __nv_bfloat16 g_h2b  [NTOK * D_];
static __device__ __nv_bfloat16 g_wfcb [HID_ * D_];
static __device__ __nv_bfloat16 g_m2b  [(size_t)NTOK * HID_];
static __device__ __nv_bfloat16 g_wprojb[D_ * HID_];

// ============================ helpers ========================================
__device__ __forceinline__ uint32_t smem_u32(const void* p) {
    uint32_t a;
    asm("{ .reg .u64 t; cvta.to.shared.u64 t, %1; cvt.u32.u64 %0, t; }" : "=r"(a) : "l"(p));
    return a;
}
__device__ __forceinline__ uint32_t f2bf2(float lo, float hi) {
    uint32_t r;
    asm("cvt.rn.bf16x2.f32 %0, %1, %2;" : "=r"(r) : "f"(hi), "f"(lo));
    return r;
}
__device__ __forceinline__ void ldsm_x4(uint32_t* r, uint32_t addr) {
    asm volatile("ldmatrix.sync.aligned.m8n8.x4.shared.b16 {%0,%1,%2,%3}, [%4];"
        : "=r"(r[0]), "=r"(r[1]), "=r"(r[2]), "=r"(r[3]) : "r"(addr));
}
__device__ __forceinline__ void ldsm_x2(uint32_t* r, uint32_t addr) {
    asm volatile("ldmatrix.sync.aligned.m8n8.x2.shared.b16 {%0,%1}, [%2];"
        : "=r"(r[0]), "=r"(r[1]) : "r"(addr));
}
__device__ __forceinline__ void mma_bf16(float* c, const uint32_t* a, const uint32_t* b) {
    asm volatile(
        "mma.sync.aligned.m16n8k16.row.col.f32.bf16.bf16.f32 "
        "{%0,%1,%2,%3}, {%4,%5,%6,%7}, {%8,%9}, {%0,%1,%2,%3};"
        : "+f"(c[0]), "+f"(c[1]), "+f"(c[2]), "+f"(c[3])
        : "r"(a[0]), "r"(a[1]), "r"(a[2]), "r"(a[3]), "r"(b[0]), "r"(b[1]));
}

// ============== bf16 mma.sync GEMM: C[M,N] = A[M,K] @ B[N,K]^T ===============
// ROUND-6 mainloop (verified best); DELTA: __launch_bounds__(256, 2) to pin
// 2 CTAs/SM (smem 40KB/CTA -> 80KB fits; reg cap 128/thread).
// 128x128 block tile, BK=32, 256 threads = 8 warps (2 warpM x 4 warpN),
// warp tile 64x32 = 4x4 m16n8k16 fragments. LDG->reg prefetch->STS,
// double-buffered static SMEM, 80B row stride.
// modes: 0: fp32 C=acc; 1: fp32 C=res+scale[col]*acc; 2: bf16 C=relu(acc)^2
#define SST 40
__global__ void __launch_bounds__(256, 2)
tmma_gemm(const __nv_bfloat16* __restrict__ A, const __nv_bfloat16* __restrict__ B,
          void* __restrict__ Cv, int N, int K, int mode,
          const float* __restrict__ res, const float* __restrict__ scale) {
    __shared__ __align__(16) uint16_t sA[2][128 * SST];
    __shared__ __align__(16) uint16_t sB[2][128 * SST];

    const int tid  = threadIdx.x;
    const int wid  = tid >> 5, lane = tid & 31;
    const int warpM = wid & 1;
    const int warpN = wid >> 1;
    const int rowBase = blockIdx.y * 128;
    const int colBase = blockIdx.x * 128;

    const int r0 = lane >> 2;
    const int c0 = lane & 3;

    float acc[4][4][4];
    #pragma unroll
    for (int mt = 0; mt < 4; mt++)
        #pragma unroll
        for (int nt = 0; nt < 4; nt++)
            #pragma unroll
            for (int i = 0; i < 4; i++) acc[mt][nt][i] = 0.f;

    const int NK = K >> 5;

    const int lr = tid >> 2;
    const int lch = (tid & 3) * 8;

    const uint32_t aBase = smem_u32(&sA[0][0]);
    const uint32_t bBase = smem_u32(&sB[0][0]);
    const uint32_t stageBytes = 128 * SST * 2;
    const uint32_t aRowOff = (uint32_t)((warpM * 64 + (lane & 15)) * SST * 2 + (lane >> 4) * 16);
    const uint32_t bRowOff = (uint32_t)((warpN * 32 + (lane & 7)) * SST * 2 + ((lane >> 3) & 1) * 16);

    #pragma unroll
    for (int it = 0; it < 2; it++) {
        int r = lr + it * 64;
        uint4 a4 = *(const uint4*)(A + (size_t)(rowBase + r) * K + lch);
        int bn = colBase + r;
        uint4 b4 = (bn < N) ? *(const uint4*)(B + (size_t)bn * K + lch)
                            : make_uint4(0u, 0u, 0u, 0u);
        *(uint4*)&sA[0][r * SST + lch] = a4;
        *(uint4*)&sB[0][r * SST + lch] = b4;
    }
    __syncthreads();

    for (int kt = 0; kt < NK; kt++) {
        const int cur = kt & 1, nxt = cur ^ 1;
        const bool have_next = (kt + 1 < NK);
        uint4 ra[2], rb[2];
        if (have_next) {
            int kb = (kt + 1) * 32;
            #pragma unroll
            for (int it = 0; it < 2; it++) {
                int r = lr + it * 64;
                ra[it] = *(const uint4*)(A + (size_t)(rowBase + r) * K + kb + lch);
                int bn = colBase + r;
                rb[it] = (bn < N) ? *(const uint4*)(B + (size_t)bn * K + kb + lch)
                                  : make_uint4(0u, 0u, 0u, 0u);
            }
        }

        const uint32_t aS = aBase + cur * stageBytes + aRowOff;
        const uint32_t bS = bBase + cur * stageBytes + bRowOff;
        #pragma unroll
        for (int ks = 0; ks < 2; ks++) {
            uint32_t af[4][4], bf[4][2];
            #pragma unroll
            for (int mt = 0; mt < 4; mt++)
                ldsm_x4(af[mt], aS + (uint32_t)(mt * 16 * SST) * 2 + ks * 32);
            #pragma unroll
            for (int nt = 0; nt < 4; nt++)
                ldsm_x2(bf[nt], bS + (uint32_t)(nt * 8 * SST) * 2 + ks * 32);
            #pragma unroll
            for (int mt = 0; mt < 4; mt++)
                #pragma unroll
                for (int nt = 0; nt < 4; nt++)
                    mma_bf16(acc[mt][nt], af[mt], bf[nt]);
        }

        if (have_next) {
            #pragma unroll
            for (int it = 0; it < 2; it++) {
                int r = lr + it * 64;
                *(uint4*)&sA[nxt][r * SST + lch] = ra[it];
                *(uint4*)&sB[nxt][r * SST + lch] = rb[it];
            }
        }
        __syncthreads();
    }

    #pragma unroll
    for (int mt = 0; mt < 4; mt++) {
        #pragma unroll
        for (int half = 0; half < 2; half++) {
            int row = rowBase + warpM * 64 + mt * 16 + r0 + half * 8;
            #pragma unroll
            for (int nt = 0; nt < 4; nt++) {
                int col = colBase + warpN * 32 + nt * 8 + 2 * c0;
                if (col < N) {
                    float v0 = acc[mt][nt][half * 2 + 0];
                    float v1 = acc[mt][nt][half * 2 + 1];
                    if (mode == 1) {
                        const float* rp = res + (size_t)row * N + col;
                        v0 = rp[0] + scale[col] * v0;
                        v1 = rp[1] + scale[col + 1] * v1;
                        *(float2*)((float*)Cv + (size_t)row * N + col) = make_float2(v0, v1);
                    } else if (mode == 2) {
                        v0 = fmaxf(v0, 0.f); v0 = v0 * v0;
                        v1 = fmaxf(v1, 0.f); v1 = v1 * v1;
                        ((uint32_t*)Cv)[((size_t)row * N + col) >> 1] = f2bf2(v0, v1);
                    } else {
                        *(float2*)((float*)Cv + (size_t)row * N + col) = make_float2(v0, v1);
                    }
                }
            }
        }
    }
}

// ---------------- fp32 -> bf16 copy ------------------------------------------
__global__ void cvt_bf16(const float* __restrict__ src, __nv_bfloat16* __restrict__ dst, int n) {
    int i = (blockIdx.x * blockDim.x + threadIdx.x) * 2;
    if (i < n) {
        float2 v = *(const float2*)(src + i);
        *(uint32_t*)(dst + i) = f2bf2(v.x, v.y);
    }
}

// ---------------- pack fused weight matrix [3088 x 544] -> bf16 --------------
__global__ void pack_wcat(const float* __restrict__ Wq, const float* __restrict__ Wk,
                          const float* __restrict__ Wv, const float* __restrict__ Wb,
                          const float* __restrict__ Wa, const float* __restrict__ Wg) {
    int idx = blockIdx.x * blockDim.x + threadIdx.x;
    if (idx >= M1 * D_) return;
    int row = idx / D_, col = idx % D_;
    float v;
    if      (row < 512)  v = Wq[row * D_ + col];
    else if (row < 1024) v = Wk[(row - 512) * D_ + col];
    else if (row < 2048) v = Wv[(row - 1024) * D_ + col];
    else if (row < 2056) v = Wb[(row - 2048) * D_ + col];
    else if (row < 2064) v = Wa[(row - 2056) * D_ + col];
    else                 v = Wg[(row - 2064) * D_ + col];
    g_wcatb[idx] = __float2bfloat16(v);
}

// ---------------- parameter-free RMSNorm over D=544 -> bf16 ------------------
__global__ void rms_kernel(const float* __restrict__ x, __nv_bfloat16* __restrict__ y) {
    int row = blockIdx.x;
    int tid = threadIdx.x;          // blockDim = 544 (17 warps)
    float v = x[(size_t)row * D_ + tid];
    float s = v * v;
    #pragma unroll
    for (int o = 16; o; o >>= 1) s += __shfl_xor_sync(0xffffffffu, s, o);
    __shared__ float ws[17];
    if ((tid & 31) == 0) ws[tid >> 5] = s;
    __syncthreads();
    if (tid < 32) {
        float t = (tid < 17) ? ws[tid] : 0.f;
        #pragma unroll
        for (int o = 16; o; o >>= 1) t += __shfl_xor_sync(0xffffffffu, t, o);
        if (tid == 0) ws[0] = t;
    }
    __syncthreads();
    float scale = rsqrtf(ws[0] * (1.0f / (float)D_) + 1e-6f);
    y[(size_t)row * D_ + tid] = __float2bfloat16(v * scale);
}

// ------- causal depthwise conv (K=4) + silu, 4 tokens per thread -------------
__global__ void conv_silu_kernel(const float* __restrict__ wq, const float* __restrict__ wk,
                                 const float* __restrict__ wv) {
    int idx = blockIdx.x * blockDim.x + threadIdx.x;   // (NTOK/4) * 2048
    if (idx >= (NTOK / 4) * 2048) return;
    int c   = idx & 2047;
    int grp = idx >> 11;
    int b   = grp >> 9;
    int t0  = (grp & 511) * 4;

    const float* w; float* outp; int ostride;
    if (c < 512)        { w = wq + c * 4;          outp = g_q + ((size_t)b * T_ + t0) * KDIM_ + c;          ostride = KDIM_; }
    else if (c < 1024)  { w = wk + (c - 512) * 4;  outp = g_k + ((size_t)b * T_ + t0) * KDIM_ + (c - 512);  ostride = KDIM_; }
    else                { w = wv + (c - 1024) * 4; outp = g_v + ((size_t)b * T_ + t0) * VDIM_ + (c - 1024); ostride = VDIM_; }

    float w0 = w[0], w1 = w[1], w2 = w[2], w3 = w[3];
    float xs[7];
    #pragma unroll
    for (int i = 0; i < 7; i++) {
        int tt = t0 - 3 + i;
        xs[i] = (tt >= 0) ? g_c1[((size_t)b * T_ + tt) * M1 + c] : 0.f;
    }
    #pragma unroll
    for (int r = 0; r < 4; r++) {
        float a = xs[r] * w0 + xs[r + 1] * w1 + xs[r + 2] * w2 + xs[r + 3] * w3;
        outp[(size_t)r * ostride] = a / (1.f + expf(-a));
    }
}

// ---------------- beta / log-decay g ----------------------------------------
__global__ void betag_kernel(const float* __restrict__ A_log, const float* __restrict__ dt_bias) {
    int idx = blockIdx.x * blockDim.x + threadIdx.x;   // NTOK * H
    if (idx >= NTOK * H_) return;
    int row = idx >> 3, h = idx & 7;
    float zb = g_c1[(size_t)row * M1 + 2048 + h];
    float za = g_c1[(size_t)row * M1 + 2056 + h];
    g_beta[idx] = 2.f / (1.f + expf(-zb));
    float z = za + dt_bias[h];
    float sp = (z > 20.f) ? z : log1pf(expf(z));
    g_g[idx] = -expf(A_log[h]) * sp;
}

// ---------------- l2-normalize q (with DK^-0.5) and k ------------------------
__global__ void l2_kernel() {
    int gwarp = (blockIdx.x * blockDim.x + threadIdx.x) >> 5;
    int lane  = threadIdx.x & 31;
    const int nvec = NTOK * H_;
    float* base; float extra;
    if (gwarp < nvec) { base = g_q + (size_t)gwarp * DK_;          extra = 0.125f; }
    else              { base = g_k + (size_t)(gwarp - nvec) * DK_; extra = 1.0f;   }
    float a = base[lane], b = base[lane + 32];
    float s = a * a + b * b;
    #pragma unroll
    for (int o = 16; o; o >>= 1) s += __shfl_xor_sync(0xffffffffu, s, o);
    float r = rsqrtf(s + 1e-6f) * extra;
    base[lane] = a * r;
    base[lane + 32] = b * r;
}

// ---------------- gated delta rule scan --------------------------------------
// ROUND-14 VERBATIM (verified best): 16-deep q/k smem ring, ONE __syncthreads
// per EIGHT timesteps. block = (b,h,vhalf): 128 CTAs, 128 threads:
// thread = jloc*2 + kh; owns S[kh*32 : kh*32+32][vhalf*64 + jloc].
__global__ void __launch_bounds__(128)
delta_kernel() {
    int bh = blockIdx.x >> 1;
    int vh = blockIdx.x & 1;
    int b = bh >> 3, h = bh & 7;
    int tid = threadIdx.x;
    int jloc = tid >> 1;
    int kh   = tid & 1;
    int j = vh * 64 + jloc;
    const int kofs = kh * 32;

    __shared__ float sq[16][64], sk[16][64];
    float S[32];
    #pragma unroll
    for (int i = 0; i < 32; i++) S[i] = 0.f;

    const size_t tok0 = (size_t)b * T_ * H_ + h;
    const float* qb = g_q + tok0 * DK_;
    const float* kb = g_k + tok0 * DK_;
    const float* vb = g_v + tok0 * DV_;
    float*       ob = g_o + tok0 * DV_;
    const float* gb = g_g + tok0;
    const float* bbp = g_beta + tok0;

    // prologue: steps 0..7 into ring slots 0..7
    float vv[16], gg[16], bbv[16];
    #pragma unroll
    for (int s = 0; s < 8; s++) {
        size_t off = (size_t)s * H_;
        if (tid < 64) sq[s][tid] = qb[off * DK_ + tid];
        else          sk[s][tid - 64] = kb[off * DK_ + (tid - 64)];
        vv[s] = vb[off * DV_ + j];
        gg[s] = gb[off];
        bbv[s] = bbp[off];
    }
    __syncthreads();

    for (int t = 0; t < T_; t += 8) {
        if (t + 8 < T_) {
            #pragma unroll
            for (int s = 0; s < 8; s++) {
                size_t off = (size_t)(t + 8 + s) * H_;
                int slot = (t + 8 + s) & 15;
                if (tid < 64) sq[slot][tid] = qb[off * DK_ + tid];
                else          sk[slot][tid - 64] = kb[off * DK_ + (tid - 64)];
                vv[8 + s] = vb[off * DV_ + j];
                gg[8 + s] = gb[off];
                bbv[8 + s] = bbp[off];
            }
        }

        #pragma unroll
        for (int s = 0; s < 8; s++) {
            const int buf = (t + s) & 15;
            float eg = expf(gg[s]);

            float kk[32];
            #pragma unroll
            for (int i = 0; i < 32; i += 4) {
                float4 t4 = *(const float4*)&sk[buf][kofs + i];
                kk[i] = t4.x; kk[i+1] = t4.y; kk[i+2] = t4.z; kk[i+3] = t4.w;
            }
            float kv0 = 0.f, kv1 = 0.f, kv2 = 0.f, kv3 = 0.f;
            #pragma unroll
            for (int i = 0; i < 32; i += 4) {
                kv0 += S[i + 0] * kk[i + 0];
                kv1 += S[i + 1] * kk[i + 1];
                kv2 += S[i + 2] * kk[i + 2];
                kv3 += S[i + 3] * kk[i + 3];
            }
            float kv = (kv0 + kv1) + (kv2 + kv3);
            kv += __shfl_xor_sync(0xffffffffu, kv, 1);
            float vres = (vv[s] - eg * kv) * bbv[s];

            float o0 = 0.f, o1 = 0.f, o2 = 0.f, o3 = 0.f;
            #pragma unroll
            for (int i = 0; i < 32; i += 4) {
                float4 q4 = *(const float4*)&sq[buf][kofs + i];
                S[i + 0] = eg * S[i + 0] + kk[i + 0] * vres; o0 += S[i + 0] * q4.x;
                S[i + 1] = eg * S[i + 1] + kk[i + 1] * vres; o1 += S[i + 1] * q4.y;
                S[i + 2] = eg * S[i + 2] + kk[i + 2] * vres; o2 += S[i + 2] * q4.z;
                S[i + 3] = eg * S[i + 3] + kk[i + 3] * vres; o3 += S[i + 3] * q4.w;
            }
            float o = (o0 + o1) + (o2 + o3);
            o += __shfl_xor_sync(0xffffffffu, o, 1);
            if (kh == 0) ob[(size_t)(t + s) * H_ * DV_ + j] = o;
        }

        #pragma unroll
        for (int s = 0; s < 8; s++) {
            vv[s] = vv[8 + s]; gg[s] = gg[8 + s]; bbv[s] = bbv[8 + s];
        }
        __syncthreads();
    }
}

// -------- gated RMSNorm on o: rms(o)*w*silu(gate) -> bf16 --------------------
__global__ void gatednorm_kernel(const float* __restrict__ o_norm_w) {
    int gvec = blockIdx.x * 8 + (threadIdx.x >> 5);   // (row, h)
    int lane = threadIdx.x & 31;
    int row = gvec >> 3, h = gvec & 7;

    const float* obase = g_o + (size_t)row * VDIM_ + h * DV_;
    float4 ov = *(const float4*)(obase + lane * 4);
    float s = ov.x * ov.x + ov.y * ov.y + ov.z * ov.z + ov.w * ov.w;
    #pragma unroll
    for (int off = 16; off; off >>= 1) s += __shfl_xor_sync(0xffffffffu, s, off);
    float scale = rsqrtf(s * (1.0f / (float)DV_) + 1e-5f);

    const float* gptr = g_c1 + (size_t)row * M1 + 2064 + h * DV_ + lane * 4;
    float4 gv = *(const float4*)gptr;
    float4 wv = *(const float4*)(o_norm_w + lane * 4);
    float r0 = ov.x * scale * wv.x * (gv.x / (1.f + expf(-gv.x)));
    float r1 = ov.y * scale * wv.y * (gv.y / (1.f + expf(-gv.y)));
    float r2 = ov.z * scale * wv.z * (gv.z / (1.f + expf(-gv.z)));
    float r3 = ov.w * scale * wv.w * (gv.w / (1.f + expf(-gv.w)));
    *(uint2*)(g_ogb + (size_t)row * VDIM_ + h * DV_ + lane * 4) =
        make_uint2(f2bf2(r0, r1), f2bf2(r2, r3));
}

// ---------------- launch ------------------------------------------------------
static inline int cdiv(int a, int b) { return (a + b - 1) / b; }

extern "C" void kernel_launch(void* const* d_in, const int* in_sizes, int n_in,
                              void* d_out, int out_size) {
    const float* x       = (const float*)d_in[0];
    const float* Wq      = (const float*)d_in[1];
    const float* Wk      = (const float*)d_in[2];
    const float* Wv      = (const float*)d_in[3];
    const float* Wb      = (const float*)d_in[4];
    const float* Wa      = (const float*)d_in[5];
    const float* Wg      = (const float*)d_in[6];
    const float* Wo      = (const float*)d_in[7];
    const float* conv_q  = (const float*)d_in[8];
    const float* conv_k  = (const float*)d_in[9];
    const float* conv_v  = (const float*)d_in[10];
    const float* A_log   = (const float*)d_in[11];
    const float* dt_bias = (const float*)d_in[12];
    const float* o_norm_w= (const float*)d_in[13];
    const float* W_fc    = (const float*)d_in[14];
    const float* W_proj  = (const float*)d_in[15];
    const float* gdn_scale = (const float*)d_in[16];
    const float* mlp_scale = (const float*)d_in[17];
    float* out = (float*)d_out;

    __nv_bfloat16 *p_hb, *p_wcatb, *p_ogb, *p_wob, *p_h2b, *p_wfcb, *p_m2b, *p_wprojb;
    float *p_c1, *p_xmid;
    cudaGetSymbolAddress((void**)&p_hb,     g_hb);
    cudaGetSymbolAddress((void**)&p_wcatb,  g_wcatb);
    cudaGetSymbolAddress((void**)&p_c1,     g_c1);
    cudaGetSymbolAddress((void**)&p_ogb,    g_ogb);
    cudaGetSymbolAddress((void**)&p_wob,    g_wob);
    cudaGetSymbolAddress((void**)&p_xmid,   g_xmid);
    cudaGetSymbolAddress((void**)&p_h2b,    g_h2b);
    cudaGetSymbolAddress((void**)&p_wfcb,   g_wfcb);
    cudaGetSymbolAddress((void**)&p_m2b,    g_m2b);
    cudaGetSymbolAddress((void**)&p_wprojb, g_wprojb);

    // 0) weight conversions (bf16-resident operands)
    pack_wcat<<<cdiv(M1 * D_, 256), 256>>>(Wq, Wk, Wv, Wb, Wa, Wg);
    cvt_bf16<<<cdiv(D_ * VDIM_ / 2, 256), 256>>>(Wo, p_wob, D_ * VDIM_);
    cvt_bf16<<<cdiv(HID_ * D_ / 2, 256), 256>>>(W_fc, p_wfcb, HID_ * D_);
    cvt_bf16<<<cdiv(D_ * HID_ / 2, 256), 256>>>(W_proj, p_wprojb, D_ * HID_);

    // 1) h = rmsnorm(x) -> bf16
    rms_kernel<<<NTOK, D_>>>(x, p_hb);

    // 2) C1 = h @ Wcat^T   (16384 x 3088), K=544
    tmma_gemm<<<dim3(cdiv(M1, 128), NTOK / 128), 256>>>(
        p_hb, p_wcatb, p_c1, M1, D_, 0, nullptr, nullptr);

    // 3) conv + silu  -> q,k,v
    conv_silu_kernel<<<cdiv((NTOK / 4) * 2048, 256), 256>>>(conv_q, conv_k, conv_v);

    // 4) beta, g
    betag_kernel<<<cdiv(NTOK * H_, 256), 256>>>(A_log, dt_bias);

    // 5) l2 norm q (with DK^-0.5), k
    l2_kernel<<<cdiv(NTOK * H_ * 2 * 32, 256), 256>>>();

    // 6) gated delta rule scan (round-14: 1 barrier per 8 steps)
    delta_kernel<<<B_ * H_ * 2, 128>>>();

    // 7) gated RMSNorm(o) * silu(gate) -> bf16
    gatednorm_kernel<<<NTOK * H_ / 8, 256>>>(o_norm_w);

    // 8) x_mid = x + gdn_scale * (og @ Wo^T), K=1024
    tmma_gemm<<<dim3(cdiv(D_, 128), NTOK / 128), 256>>>(
        p_ogb, p_wob, p_xmid, D_, VDIM_, 1, x, gdn_scale);

    // 9) h2 = rmsnorm(x_mid) -> bf16
    rms_kernel<<<NTOK, D_>>>(p_xmid, p_h2b);

    // 10) m2 = relu(h2 @ W_fc^T)^2 -> bf16, K=544
    tmma_gemm<<<dim3(cdiv(HID_, 128), NTOK / 128), 256>>>(
        p_h2b, p_wfcb, p_m2b, HID_, D_, 2, nullptr, nullptr);

    // 11) out = x_mid + mlp_scale * (m2 @ W_proj^T), K=1632
    tmma_gemm<<<dim3(cdiv(D_, 128), NTOK / 128), 256>>>(
        p_m2b, p_wprojb, out, D_, HID_, 1, p_xmid, mlp_scale);
}